// round 6
// baseline (speedup 1.0000x reference)
#include <cuda_runtime.h>
#include <cstdint>

#define FDIM 128
#define MAXN 50176   // 50000 rounded up to 128-row tiles

// Scratch (allocation-free rule: __device__ globals)
__device__ float g_Ws[FDIM * FDIM];
__device__ float g_G[(size_t)MAXN * FDIM];
__device__ int   g_idx64;   // 1 if index arrays are int64, 0 if int32

// ---------------------------------------------------------------------------
// Kernel 0: detect index dtype. Sample odd 32-bit words within the first half
// of the mol-id buffer (in-bounds under either dtype interpretation).
//   int64 data: word[2e+1] = high word of value < 1024  -> always 0
//   int32 data: word[2e+1] = a real mol id in [0,1024)  -> nonzero w.p. 1023/1024
// ---------------------------------------------------------------------------
__global__ void detect_kernel(const void* __restrict__ mol, long long E) {
    const int* p = (const int*)mol;
    __shared__ int nonzero;
    if (threadIdx.x == 0) nonzero = 0;
    __syncthreads();
    long long half = E / 2;
    for (int s = threadIdx.x; s < 1024; s += blockDim.x) {
        long long e = (half * s) / 1024;      // e in [0, half)
        if (p[2 * e + 1] != 0) atomicExch(&nonzero, 1);
    }
    __syncthreads();
    if (threadIdx.x == 0) g_idx64 = (nonzero == 0) ? 1 : 0;
}

// ---------------------------------------------------------------------------
// Kernel 1: Ws = W + W^T
// ---------------------------------------------------------------------------
__global__ void ws_kernel(const float* __restrict__ W) {
    int i = blockIdx.x;
    int j = threadIdx.x;
    g_Ws[i * FDIM + j] = W[i * FDIM + j] + W[j * FDIM + i];
}

// ---------------------------------------------------------------------------
// Kernel 2: G = X @ Ws   (N x 128) = (N x 128)(128 x 128)
// f32x2 packed FMA (FFMA2) for 2x fp32 throughput on sm_103a.
// Block: 256 threads, tile 128 rows x 128 cols, BK=16, 8x8 per thread
// (accumulated as 8 rows x 4 packed col-pairs).
// ---------------------------------------------------------------------------
__device__ __forceinline__ unsigned long long dup2(float x) {
    unsigned u = __float_as_uint(x);
    return ((unsigned long long)u << 32) | (unsigned long long)u;
}

__device__ __forceinline__ unsigned long long ffma2(unsigned long long a,
                                                    unsigned long long b,
                                                    unsigned long long c) {
    unsigned long long d;
    asm("fma.rn.f32x2 %0, %1, %2, %3;" : "=l"(d) : "l"(a), "l"(b), "l"(c));
    return d;
}

__global__ __launch_bounds__(256, 2) void gemm_kernel(const float* __restrict__ X, int N) {
    __shared__ unsigned long long Xs2[16][128];  // Xs2[k][m] = {x, x} duplicated pair (16KB)
    __shared__ float Wss[16][128];               // Ws chunk, row k0+k (8KB)

    const int tid  = threadIdx.x;
    const int cx   = tid & 15;   // col group: cols cx*8 .. cx*8+7
    const int cy   = tid >> 4;   // row group: rows cy*8 .. cy*8+7
    const int row0 = blockIdx.x * 128;

    unsigned long long acc[8][4];
#pragma unroll
    for (int i = 0; i < 8; i++)
#pragma unroll
        for (int j = 0; j < 4; j++) acc[i][j] = 0ull;

    for (int k0 = 0; k0 < FDIM; k0 += 16) {
        // Load X tile (128 rows x 16 cols) as duplicated f32 pairs
#pragma unroll
        for (int t = 0; t < 2; t++) {
            int l  = tid + t * 256;       // 512 float4s
            int m  = l >> 2;              // row within tile
            int kq = (l & 3) * 4;         // k offset
            int gr = row0 + m;
            float4 v = (gr < N) ? *(const float4*)(X + (size_t)gr * FDIM + k0 + kq)
                                : make_float4(0.f, 0.f, 0.f, 0.f);
            Xs2[kq + 0][m] = dup2(v.x);
            Xs2[kq + 1][m] = dup2(v.y);
            Xs2[kq + 2][m] = dup2(v.z);
            Xs2[kq + 3][m] = dup2(v.w);
        }
        // Load Ws chunk (16 rows x 128 cols)
#pragma unroll
        for (int t = 0; t < 2; t++) {
            int l  = tid + t * 256;       // 512 float4s
            int kk = l >> 5;
            int c  = (l & 31) * 4;
            *(float4*)&Wss[kk][c] = *(const float4*)&g_Ws[(k0 + kk) * FDIM + c];
        }
        __syncthreads();

#pragma unroll
        for (int k = 0; k < 16; k++) {
            unsigned long long xr[8];
#pragma unroll
            for (int h = 0; h < 4; h++) {
                ulonglong2 xp = *(const ulonglong2*)&Xs2[k][cy * 8 + h * 2];
                xr[h * 2 + 0] = xp.x;
                xr[h * 2 + 1] = xp.y;
            }
            ulonglong2 wp0 = *(const ulonglong2*)&Wss[k][cx * 8];
            ulonglong2 wp1 = *(const ulonglong2*)&Wss[k][cx * 8 + 4];
            unsigned long long wc[4] = {wp0.x, wp0.y, wp1.x, wp1.y};
#pragma unroll
            for (int i = 0; i < 8; i++)
#pragma unroll
                for (int j = 0; j < 4; j++)
                    acc[i][j] = ffma2(xr[i], wc[j], acc[i][j]);
        }
        __syncthreads();
    }

#pragma unroll
    for (int i = 0; i < 8; i++) {
        int gr = row0 + cy * 8 + i;
        if (gr < N) {
            ulonglong2 s0; s0.x = acc[i][0]; s0.y = acc[i][1];
            ulonglong2 s1; s1.x = acc[i][2]; s1.y = acc[i][3];
            *(ulonglong2*)&g_G[(size_t)gr * FDIM + cx * 8 + 0] = s0;
            *(ulonglong2*)&g_G[(size_t)gr * FDIM + cx * 8 + 4] = s1;
        }
    }
}

// ---------------------------------------------------------------------------
// Kernel 3: per-edge dot + segment sum.
// One warp per edge; float4 per lane (128 floats = 32 lanes x 4).
// Block-local smem accumulator (M floats) keeps global atomics cheap.
// Index dtype (int32 vs int64) selected by g_idx64 flag (uniform branch).
// ---------------------------------------------------------------------------
__global__ void edge_kernel(const float* __restrict__ X,
                            const void* __restrict__ nbr,
                            const void* __restrict__ mol,
                            long long E,
                            float* __restrict__ out,
                            int M) {
    extern __shared__ float acc[];
    for (int t = threadIdx.x; t < M; t += blockDim.x) acc[t] = 0.f;
    __syncthreads();

    const int lane = threadIdx.x & 31;
    const bool i64 = (g_idx64 != 0);
    long long w  = ((long long)blockIdx.x * blockDim.x + threadIdx.x) >> 5;
    long long nw = ((long long)gridDim.x * blockDim.x) >> 5;

    const long long* nbr64 = (const long long*)nbr;
    const long long* mol64 = (const long long*)mol;
    const int*       nbr32 = (const int*)nbr;
    const int*       mol32 = (const int*)mol;

    for (long long e = w; e < E; e += nw) {
        long long i, j;
        int m;
        if (i64) {
            i = nbr64[e];
            j = nbr64[E + e];
            m = (int)mol64[e];
        } else {
            i = nbr32[e];
            j = nbr32[E + e];
            m = mol32[e];
        }
        float4 a = *(const float4*)(g_G + (size_t)i * FDIM + lane * 4);
        float4 b = *(const float4*)(X   + (size_t)j * FDIM + lane * 4);
        float s = a.x * b.x + a.y * b.y + a.z * b.z + a.w * b.w;
        s += __shfl_down_sync(0xffffffffu, s, 16);
        s += __shfl_down_sync(0xffffffffu, s, 8);
        s += __shfl_down_sync(0xffffffffu, s, 4);
        s += __shfl_down_sync(0xffffffffu, s, 2);
        s += __shfl_down_sync(0xffffffffu, s, 1);
        if (lane == 0) atomicAdd(&acc[m], s);
    }

    __syncthreads();
    for (int t = threadIdx.x; t < M; t += blockDim.x)
        atomicAdd(&out[t], acc[t]);
}

// ---------------------------------------------------------------------------
// Launch
// ---------------------------------------------------------------------------
extern "C" void kernel_launch(void* const* d_in, const int* in_sizes, int n_in,
                              void* d_out, int out_size) {
    const float* X  = (const float*)d_in[0];   // [N, 128] fp32
    const float* W  = (const float*)d_in[1];   // [128, 128] fp32
    const void*  nbr = d_in[2];                // [2, E] int32 or int64
    const void*  mol = d_in[3];                // [E]    int32 or int64
    float* out = (float*)d_out;                // [M] fp32

    const long long E = (long long)in_sizes[3];   // element count, dtype-invariant
    const int N = in_sizes[0] / FDIM;

    // out is poisoned; zero it (capturable async memset)
    cudaMemsetAsync(d_out, 0, (size_t)out_size * sizeof(float), 0);

    detect_kernel<<<1, 256>>>(mol, E);

    ws_kernel<<<FDIM, FDIM>>>(W);

    int gemm_blocks = (N + 127) / 128;
    gemm_kernel<<<gemm_blocks, 256>>>(X, N);

    // 592 blocks x 512 threads = 9472 warps: ~9 MB of loads in flight,
    // well above the ~1.6 MB needed to cover ~250cyc L2 latency at LTS cap.
    int eblocks = 592;
    size_t smem = (size_t)out_size * sizeof(float);
    edge_kernel<<<eblocks, 512, smem>>>(X, nbr, mol, E, out, out_size);
}

// round 8
// speedup vs baseline: 1.2935x; 1.2935x over previous
#include <cuda_runtime.h>
#include <cstdint>

#define FDIM 128
#define MAXN 50176   // 50000 rounded up to 128-row tiles

// Scratch (allocation-free rule: __device__ globals)
__device__ float g_Ws[FDIM * FDIM];
__device__ float g_G[(size_t)MAXN * FDIM];
__device__ int   g_idx64;   // 1 if index arrays are int64, 0 if int32

// ---------------------------------------------------------------------------
// Kernel 0: detect index dtype (validated in R6).
// ---------------------------------------------------------------------------
__global__ void detect_kernel(const void* __restrict__ mol, long long E) {
    const int* p = (const int*)mol;
    __shared__ int nonzero;
    if (threadIdx.x == 0) nonzero = 0;
    __syncthreads();
    long long half = E / 2;
    for (int s = threadIdx.x; s < 1024; s += blockDim.x) {
        long long e = (half * s) / 1024;
        if (p[2 * e + 1] != 0) atomicExch(&nonzero, 1);
    }
    __syncthreads();
    if (threadIdx.x == 0) g_idx64 = (nonzero == 0) ? 1 : 0;
}

// ---------------------------------------------------------------------------
// Kernel 1: Ws = W + W^T
// ---------------------------------------------------------------------------
__global__ void ws_kernel(const float* __restrict__ W) {
    int i = blockIdx.x;
    int j = threadIdx.x;
    g_Ws[i * FDIM + j] = W[i * FDIM + j] + W[j * FDIM + i];
}

// ---------------------------------------------------------------------------
// Kernel 2: G = X @ Ws (f32x2 packed FMA). ~11us measured — at FFMA2 floor.
// ---------------------------------------------------------------------------
__device__ __forceinline__ unsigned long long dup2(float x) {
    unsigned u = __float_as_uint(x);
    return ((unsigned long long)u << 32) | (unsigned long long)u;
}

__device__ __forceinline__ unsigned long long ffma2(unsigned long long a,
                                                    unsigned long long b,
                                                    unsigned long long c) {
    unsigned long long d;
    asm("fma.rn.f32x2 %0, %1, %2, %3;" : "=l"(d) : "l"(a), "l"(b), "l"(c));
    return d;
}

__global__ __launch_bounds__(256, 2) void gemm_kernel(const float* __restrict__ X, int N) {
    __shared__ unsigned long long Xs2[16][128];
    __shared__ float Wss[16][128];

    const int tid  = threadIdx.x;
    const int cx   = tid & 15;
    const int cy   = tid >> 4;
    const int row0 = blockIdx.x * 128;

    unsigned long long acc[8][4];
#pragma unroll
    for (int i = 0; i < 8; i++)
#pragma unroll
        for (int j = 0; j < 4; j++) acc[i][j] = 0ull;

    for (int k0 = 0; k0 < FDIM; k0 += 16) {
#pragma unroll
        for (int t = 0; t < 2; t++) {
            int l  = tid + t * 256;
            int m  = l >> 2;
            int kq = (l & 3) * 4;
            int gr = row0 + m;
            float4 v = (gr < N) ? *(const float4*)(X + (size_t)gr * FDIM + k0 + kq)
                                : make_float4(0.f, 0.f, 0.f, 0.f);
            Xs2[kq + 0][m] = dup2(v.x);
            Xs2[kq + 1][m] = dup2(v.y);
            Xs2[kq + 2][m] = dup2(v.z);
            Xs2[kq + 3][m] = dup2(v.w);
        }
#pragma unroll
        for (int t = 0; t < 2; t++) {
            int l  = tid + t * 256;
            int kk = l >> 5;
            int c  = (l & 31) * 4;
            *(float4*)&Wss[kk][c] = *(const float4*)&g_Ws[(k0 + kk) * FDIM + c];
        }
        __syncthreads();

#pragma unroll
        for (int k = 0; k < 16; k++) {
            unsigned long long xr[8];
#pragma unroll
            for (int h = 0; h < 4; h++) {
                ulonglong2 xp = *(const ulonglong2*)&Xs2[k][cy * 8 + h * 2];
                xr[h * 2 + 0] = xp.x;
                xr[h * 2 + 1] = xp.y;
            }
            ulonglong2 wp0 = *(const ulonglong2*)&Wss[k][cx * 8];
            ulonglong2 wp1 = *(const ulonglong2*)&Wss[k][cx * 8 + 4];
            unsigned long long wc[4] = {wp0.x, wp0.y, wp1.x, wp1.y};
#pragma unroll
            for (int i = 0; i < 8; i++)
#pragma unroll
                for (int j = 0; j < 4; j++)
                    acc[i][j] = ffma2(xr[i], wc[j], acc[i][j]);
        }
        __syncthreads();
    }

#pragma unroll
    for (int i = 0; i < 8; i++) {
        int gr = row0 + cy * 8 + i;
        if (gr < N) {
            ulonglong2 s0; s0.x = acc[i][0]; s0.y = acc[i][1];
            ulonglong2 s1; s1.x = acc[i][2]; s1.y = acc[i][3];
            *(ulonglong2*)&g_G[(size_t)gr * FDIM + cx * 8 + 0] = s0;
            *(ulonglong2*)&g_G[(size_t)gr * FDIM + cx * 8 + 4] = s1;
        }
    }
}

// ---------------------------------------------------------------------------
// Kernel 3: edge dot + segment sum, 4 edges per warp per iteration.
// 8 LDG.128 in flight per warp (4KB), int4 index loads, 4 interleaved
// shuffle-reduction chains, single 4-lane smem atomic per chunk.
// ---------------------------------------------------------------------------
__device__ __forceinline__ float dot4(float4 a, float4 b) {
    return fmaf(a.x, b.x, fmaf(a.y, b.y, fmaf(a.z, b.z, a.w * b.w)));
}

__global__ __launch_bounds__(256)
void edge_kernel(const float* __restrict__ X,
                 const void* __restrict__ nbr,
                 const void* __restrict__ mol,
                 long long E,
                 float* __restrict__ out,
                 int M) {
    extern __shared__ float acc[];
    for (int t = threadIdx.x; t < M; t += blockDim.x) acc[t] = 0.f;
    __syncthreads();

    const int lane = threadIdx.x & 31;
    const float4* __restrict__ A = (const float4*)g_G;
    const float4* __restrict__ B = (const float4*)X;
    const long long w  = ((long long)blockIdx.x * blockDim.x + threadIdx.x) >> 5;
    const long long nw = ((long long)gridDim.x * blockDim.x) >> 5;

    if (g_idx64 == 0) {
        // ---- int32 path (the real data path) ----
        const int* __restrict__ src = (const int*)nbr;
        const int* __restrict__ dst = src + E;
        const int* __restrict__ mm  = (const int*)mol;

        for (long long e0 = w * 4; e0 < E; e0 += nw * 4) {
            int i0, i1, i2, i3, j0, j1, j2, j3, m0, m1, m2, m3;
            float v1 = 1.f, v2 = 1.f, v3 = 1.f;
            if (e0 + 4 <= E) {
                int4 si = *(const int4*)(src + e0);
                int4 sj = *(const int4*)(dst + e0);
                int4 sm = *(const int4*)(mm + e0);
                i0 = si.x; i1 = si.y; i2 = si.z; i3 = si.w;
                j0 = sj.x; j1 = sj.y; j2 = sj.z; j3 = sj.w;
                m0 = sm.x; m1 = sm.y; m2 = sm.z; m3 = sm.w;
            } else {
                i0 = src[e0]; j0 = dst[e0]; m0 = mm[e0];
                i1 = i2 = i3 = 0; j1 = j2 = j3 = 0; m1 = m2 = m3 = 0;
                v1 = v2 = v3 = 0.f;
                if (e0 + 1 < E) { i1 = src[e0+1]; j1 = dst[e0+1]; m1 = mm[e0+1]; v1 = 1.f; }
                if (e0 + 2 < E) { i2 = src[e0+2]; j2 = dst[e0+2]; m2 = mm[e0+2]; v2 = 1.f; }
                if (e0 + 3 < E) { i3 = src[e0+3]; j3 = dst[e0+3]; m3 = mm[e0+3]; v3 = 1.f; }
            }

            // 8 independent gathers — all issue before first dot consumes
            float4 a0 = A[(size_t)i0 * 32 + lane];
            float4 b0 = B[(size_t)j0 * 32 + lane];
            float4 a1 = A[(size_t)i1 * 32 + lane];
            float4 b1 = B[(size_t)j1 * 32 + lane];
            float4 a2 = A[(size_t)i2 * 32 + lane];
            float4 b2 = B[(size_t)j2 * 32 + lane];
            float4 a3 = A[(size_t)i3 * 32 + lane];
            float4 b3 = B[(size_t)j3 * 32 + lane];

            float s0 = dot4(a0, b0);
            float s1 = dot4(a1, b1) * v1;
            float s2 = dot4(a2, b2) * v2;
            float s3 = dot4(a3, b3) * v3;

#pragma unroll
            for (int o = 16; o; o >>= 1) {
                s0 += __shfl_xor_sync(0xffffffffu, s0, o);
                s1 += __shfl_xor_sync(0xffffffffu, s1, o);
                s2 += __shfl_xor_sync(0xffffffffu, s2, o);
                s3 += __shfl_xor_sync(0xffffffffu, s3, o);
            }

            float sv = (lane == 0) ? s0 : (lane == 1) ? s1 : (lane == 2) ? s2 : s3;
            int   mv = (lane == 0) ? m0 : (lane == 1) ? m1 : (lane == 2) ? m2 : m3;
            if (lane < 4) atomicAdd(&acc[mv], sv);
        }
    } else {
        // ---- int64 fallback (correctness only) ----
        const long long* __restrict__ src = (const long long*)nbr;
        const long long* __restrict__ dst = src + E;
        const long long* __restrict__ mm  = (const long long*)mol;
        for (long long e = w; e < E; e += nw) {
            long long i = src[e];
            long long j = dst[e];
            float4 a = A[(size_t)i * 32 + lane];
            float4 b = B[(size_t)j * 32 + lane];
            float s = dot4(a, b);
#pragma unroll
            for (int o = 16; o; o >>= 1) s += __shfl_xor_sync(0xffffffffu, s, o);
            if (lane == 0) atomicAdd(&acc[(int)mm[e]], s);
        }
    }

    __syncthreads();
    for (int t = threadIdx.x; t < M; t += blockDim.x)
        atomicAdd(&out[t], acc[t]);
}

// ---------------------------------------------------------------------------
// Launch
// ---------------------------------------------------------------------------
extern "C" void kernel_launch(void* const* d_in, const int* in_sizes, int n_in,
                              void* d_out, int out_size) {
    const float* X  = (const float*)d_in[0];   // [N, 128] fp32
    const float* W  = (const float*)d_in[1];   // [128, 128] fp32
    const void*  nbr = d_in[2];                // [2, E] int32 (detected) or int64
    const void*  mol = d_in[3];                // [E]
    float* out = (float*)d_out;                // [M] fp32

    const long long E = (long long)in_sizes[3];
    const int N = in_sizes[0] / FDIM;

    cudaMemsetAsync(d_out, 0, (size_t)out_size * sizeof(float), 0);

    detect_kernel<<<1, 256>>>(mol, E);

    ws_kernel<<<FDIM, FDIM>>>(W);   // <-- was missing in R7: g_Ws stayed zero

    int gemm_blocks = (N + 127) / 128;
    gemm_kernel<<<gemm_blocks, 256>>>(X, N);

    // 592 blocks x 256 threads, grid-stride over 4-edge chunks.
    int eblocks = 592;
    size_t smem = (size_t)out_size * sizeof(float);
    edge_kernel<<<eblocks, 256, smem>>>(X, nbr, mol, E, out, out_size);
}